// round 1
// baseline (speedup 1.0000x reference)
#include <cuda_runtime.h>
#include <cstddef>
#include <math.h>

#define B_   8
#define C_   512
#define NPIX 4096
#define NH   8
#define HD   64

// ---------------- scratch (static device arrays; no allocation) ----------------
__device__ float g_sx  [B_ * C_];            // column sums of x
__device__ float g_Xg  [B_ * C_ * C_];       // Gram per batch
__device__ float g_A2  [B_ * C_ * C_];       // Wq @ Xg per batch
__device__ float g_qs  [B_ * C_];            // Wq @ sx
__device__ float g_ks  [B_ * C_];            // Wk @ sx
__device__ float g_attn[B_ * HD * NH * NH];  // softmax result
__device__ float g_Wve [B_ * C_ * C_];       // effective V projection (row m, col c)
__device__ float g_bve [B_ * C_];            // effective V bias
__device__ float g_Mp  [B_ * C_ * C_];       // gamma*Wo@Wve + I
__device__ float g_be  [B_ * C_];            // final effective bias

// ---------------- generic tiled SGEMM ----------------
// C[M,N] = alpha * A[M,K] x B  (+bias[row]) (+I)
// TRANSB=true : B is [N,K] row-major (C = A * B^T)
// TRANSB=false: B is [K,N] row-major (C = A * B)
// All of M,N multiples of 128 and K multiple of 8 (guaranteed by caller).
constexpr int BM = 128, BN = 128, BK = 8, TM = 8, TN = 8;

template <bool TRANSB, bool IDENT, bool BIAS>
__global__ void __launch_bounds__(256, 2) sgemm_kernel(
    const float* __restrict__ A, const float* __restrict__ Bm,
    float* __restrict__ Cm, const float* __restrict__ bias,
    const float* __restrict__ alpha_ptr,
    int M, int N, int K,
    size_t strideA, size_t strideB, size_t strideC, size_t strideBias)
{
    __shared__ float As[BK][BM];
    __shared__ float Bs[BK][BN];

    const int bz = blockIdx.z;
    const float* Ab = A  + (size_t)bz * strideA;
    const float* Bb = Bm + (size_t)bz * strideB;
    float*       Cb = Cm + (size_t)bz * strideC;

    const int m0 = blockIdx.y * BM;
    const int n0 = blockIdx.x * BN;
    const int tid = threadIdx.x;
    const int tx = tid & 15;        // 16 cols of threads
    const int ty = tid >> 4;        // 16 rows of threads

    // global->smem load indices
    const int ar  = tid >> 1;           // 0..127 (tile row)
    const int ac  = (tid & 1) * 4;      // 0 or 4 (k group)
    const int bkr = tid >> 5;           // 0..7   (NN: k row)
    const int bnc = (tid & 31) * 4;     // 0..124 (NN: n group)

    float acc[TM][TN];
    #pragma unroll
    for (int i = 0; i < TM; i++)
        #pragma unroll
        for (int j = 0; j < TN; j++) acc[i][j] = 0.f;

    for (int k0 = 0; k0 < K; k0 += BK) {
        float4 av = *(const float4*)(Ab + (size_t)(m0 + ar) * K + (k0 + ac));
        As[ac + 0][ar] = av.x;
        As[ac + 1][ar] = av.y;
        As[ac + 2][ar] = av.z;
        As[ac + 3][ar] = av.w;
        if (TRANSB) {
            float4 bv = *(const float4*)(Bb + (size_t)(n0 + ar) * K + (k0 + ac));
            Bs[ac + 0][ar] = bv.x;
            Bs[ac + 1][ar] = bv.y;
            Bs[ac + 2][ar] = bv.z;
            Bs[ac + 3][ar] = bv.w;
        } else {
            float4 bv = *(const float4*)(Bb + (size_t)(k0 + bkr) * N + (n0 + bnc));
            *(float4*)&Bs[bkr][bnc] = bv;
        }
        __syncthreads();

        #pragma unroll
        for (int kk = 0; kk < BK; kk++) {
            float a[TM], b[TN];
            *(float4*)&a[0] = *(const float4*)&As[kk][ty * TM + 0];
            *(float4*)&a[4] = *(const float4*)&As[kk][ty * TM + 4];
            *(float4*)&b[0] = *(const float4*)&Bs[kk][tx * TN + 0];
            *(float4*)&b[4] = *(const float4*)&Bs[kk][tx * TN + 4];
            #pragma unroll
            for (int i = 0; i < TM; i++)
                #pragma unroll
                for (int j = 0; j < TN; j++)
                    acc[i][j] += a[i] * b[j];
        }
        __syncthreads();
    }

    const float alpha = alpha_ptr ? alpha_ptr[0] : 1.0f;

    #pragma unroll
    for (int i = 0; i < TM; i++) {
        const int row = m0 + ty * TM + i;
        float badd = 0.f;
        if (BIAS) badd = bias[(size_t)bz * strideBias + row];
        #pragma unroll
        for (int j = 0; j < TN; j += 4) {
            const int col = n0 + tx * TN + j;
            float4 v;
            v.x = alpha * acc[i][j + 0] + badd;
            v.y = alpha * acc[i][j + 1] + badd;
            v.z = alpha * acc[i][j + 2] + badd;
            v.w = alpha * acc[i][j + 3] + badd;
            if (IDENT) {
                if (row == col + 0) v.x += 1.f;
                if (row == col + 1) v.y += 1.f;
                if (row == col + 2) v.z += 1.f;
                if (row == col + 3) v.w += 1.f;
            }
            *(float4*)(Cb + (size_t)row * N + col) = v;
        }
    }
}

// ---------------- small kernels ----------------

// sx[b,c] = sum_n x[b,c,n]
__global__ void colsum_kernel(const float* __restrict__ x, float* __restrict__ sx)
{
    const int c = blockIdx.x, b = blockIdx.y;
    const float* p = x + ((size_t)b * C_ + c) * NPIX;
    float s = 0.f;
    for (int n = threadIdx.x; n < NPIX; n += 256) s += p[n];
    __shared__ float red[256];
    red[threadIdx.x] = s;
    __syncthreads();
    for (int off = 128; off > 0; off >>= 1) {
        if (threadIdx.x < off) red[threadIdx.x] += red[threadIdx.x + off];
        __syncthreads();
    }
    if (threadIdx.x == 0) sx[b * C_ + c] = red[0];
}

// qs[b,c] = Wq[c,:].sx[b,:] ; ks[b,c] = Wk[c,:].sx[b,:]
__global__ void projsum_kernel(const float* __restrict__ Wq, const float* __restrict__ Wk,
                               const float* __restrict__ sx,
                               float* __restrict__ qs, float* __restrict__ ks)
{
    const int gw   = (blockIdx.x * blockDim.x + threadIdx.x) >> 5;
    const int lane = threadIdx.x & 31;
    if (gw >= 2 * B_ * C_) return;
    const int which = gw >> 12;           // 0 => qs, 1 => ks (4096 each)
    const int idx = gw & 4095;
    const int b = idx >> 9, c = idx & 511;
    const float* W = which ? Wk : Wq;
    const float* s = sx + b * C_;
    float acc = 0.f;
    for (int k = lane; k < C_; k += 32) acc += W[(size_t)c * C_ + k] * s[k];
    #pragma unroll
    for (int off = 16; off; off >>= 1) acc += __shfl_down_sync(0xffffffffu, acc, off);
    if (lane == 0) (which ? ks : qs)[b * C_ + c] = acc;
}

// S[b,d,i,j] + softmax over j -> attn.  One block per (b,d,i); warp j does the 512-dot.
__global__ void attn_kernel(const float* __restrict__ A2, const float* __restrict__ Wk,
                            const float* __restrict__ bq, const float* __restrict__ bk,
                            const float* __restrict__ qs, const float* __restrict__ ks,
                            float* __restrict__ attn)
{
    const int bid = blockIdx.x;           // ((b*64+d)*8+i)
    const int i = bid & 7;
    const int bd = bid >> 3;
    const int d = bd & 63, b = bd >> 6;
    const int j = threadIdx.x >> 5, lane = threadIdx.x & 31;
    const int id = i * HD + d, jd = j * HD + d;

    const float* a2 = A2 + ((size_t)b * C_ + id) * C_;
    const float* wk = Wk + (size_t)jd * C_;
    float acc = 0.f;
    for (int c = lane; c < C_; c += 32) acc += a2[c] * wk[c];
    #pragma unroll
    for (int off = 16; off; off >>= 1) acc += __shfl_down_sync(0xffffffffu, acc, off);

    __shared__ float Sj[NH];
    if (lane == 0) {
        float s = acc + bq[id] * ks[b * C_ + jd] + qs[b * C_ + id] * bk[jd]
                + (float)NPIX * bq[id] * bk[jd];
        Sj[j] = s * 0.125f;               // / sqrt(hd) = / 8
    }
    __syncthreads();
    if (threadIdx.x < NH) {
        float mx = -1e30f;
        #pragma unroll
        for (int t = 0; t < NH; t++) mx = fmaxf(mx, Sj[t]);
        float sum = 0.f;
        #pragma unroll
        for (int t = 0; t < NH; t++) sum += expf(Sj[t] - mx);
        attn[(size_t)bid * NH + threadIdx.x] = expf(Sj[threadIdx.x] - mx) / sum;
    }
}

// Wve[b,m,c] = sum_j attn[b,d,i,j] * Wv[j*64+d, c]  (m = i*64+d); bve likewise from bv
__global__ void wve_kernel(const float* __restrict__ Wv, const float* __restrict__ bv,
                           const float* __restrict__ attn,
                           float* __restrict__ Wve, float* __restrict__ bve)
{
    const int m = blockIdx.x, b = blockIdx.y;
    const int d = m & 63, i = m >> 6;
    const float* at = attn + (((size_t)b * HD + d) * NH + i) * NH;
    float a[NH];
    #pragma unroll
    for (int j = 0; j < NH; j++) a[j] = at[j];

    for (int c = threadIdx.x; c < C_; c += 256) {
        float acc = 0.f;
        #pragma unroll
        for (int j = 0; j < NH; j++) acc += a[j] * Wv[(size_t)(j * HD + d) * C_ + c];
        Wve[((size_t)b * C_ + m) * C_ + c] = acc;
    }
    if (threadIdx.x == 0) {
        float accb = 0.f;
        #pragma unroll
        for (int j = 0; j < NH; j++) accb += a[j] * bv[j * HD + d];
        bve[b * C_ + m] = accb;
    }
}

// be[b,o] = gamma * Wo[o,:].bve[b,:] + bo[o]
__global__ void biaseff_kernel(const float* __restrict__ Wo, const float* __restrict__ bo,
                               const float* __restrict__ bve, const float* __restrict__ gamma,
                               float* __restrict__ be)
{
    const int gw   = (blockIdx.x * blockDim.x + threadIdx.x) >> 5;
    const int lane = threadIdx.x & 31;
    if (gw >= B_ * C_) return;
    const int b = gw >> 9, o = gw & 511;
    float acc = 0.f;
    for (int mm = lane; mm < C_; mm += 32) acc += Wo[(size_t)o * C_ + mm] * bve[b * C_ + mm];
    #pragma unroll
    for (int off = 16; off; off >>= 1) acc += __shfl_down_sync(0xffffffffu, acc, off);
    if (lane == 0) be[b * C_ + o] = gamma[0] * acc + bo[o];
}

// ---------------- launch ----------------
extern "C" void kernel_launch(void* const* d_in, const int* in_sizes, int n_in,
                              void* d_out, int out_size)
{
    (void)in_sizes; (void)n_in; (void)out_size;
    const float* x     = (const float*)d_in[0];
    const float* Wq    = (const float*)d_in[1];
    const float* bq    = (const float*)d_in[2];
    const float* Wk    = (const float*)d_in[3];
    const float* bk    = (const float*)d_in[4];
    const float* Wv    = (const float*)d_in[5];
    const float* bv    = (const float*)d_in[6];
    const float* Wo    = (const float*)d_in[7];
    const float* bo    = (const float*)d_in[8];
    const float* gamma = (const float*)d_in[9];
    float* out = (float*)d_out;

    float *sx, *Xg, *A2, *qs, *ks, *attn, *Wve, *bve, *Mp, *be;
    cudaGetSymbolAddress((void**)&sx,   g_sx);
    cudaGetSymbolAddress((void**)&Xg,   g_Xg);
    cudaGetSymbolAddress((void**)&A2,   g_A2);
    cudaGetSymbolAddress((void**)&qs,   g_qs);
    cudaGetSymbolAddress((void**)&ks,   g_ks);
    cudaGetSymbolAddress((void**)&attn, g_attn);
    cudaGetSymbolAddress((void**)&Wve,  g_Wve);
    cudaGetSymbolAddress((void**)&bve,  g_bve);
    cudaGetSymbolAddress((void**)&Mp,   g_Mp);
    cudaGetSymbolAddress((void**)&be,   g_be);

    const size_t CN = (size_t)C_ * NPIX;   // per-batch x stride
    const size_t CC = (size_t)C_ * C_;

    // 1) column sums
    colsum_kernel<<<dim3(C_, B_), 256>>>(x, sx);

    // 2) Gram: Xg[b] = x_b * x_b^T   (NT, M=N=512, K=4096)
    sgemm_kernel<true, false, false><<<dim3(C_ / BN, C_ / BM, B_), 256>>>(
        x, x, Xg, nullptr, nullptr, C_, C_, NPIX, CN, CN, CC, 0);

    // 3) projected sums
    projsum_kernel<<<(2 * B_ * C_ * 32 + 255) / 256, 256>>>(Wq, Wk, sx, qs, ks);

    // 4) A2[b] = Wq * Xg[b]  (use symmetry: NT with B = Xg)
    sgemm_kernel<true, false, false><<<dim3(C_ / BN, C_ / BM, B_), 256>>>(
        Wq, Xg, A2, nullptr, nullptr, C_, C_, C_, 0, CC, CC, 0);

    // 5) logits + softmax -> attn
    attn_kernel<<<B_ * HD * NH, 256>>>(A2, Wk, bq, bk, qs, ks, attn);

    // 6) effective V projection
    wve_kernel<<<dim3(C_, B_), 256>>>(Wv, bv, attn, Wve, bve);

    // 7) Mp[b] = gamma * Wo * Wve[b] + I   (NN, alpha from device gamma)
    sgemm_kernel<false, true, false><<<dim3(C_ / BN, C_ / BM, B_), 256>>>(
        Wo, Wve, Mp, nullptr, gamma, C_, C_, C_, 0, CC, CC, 0);

    // 8) effective bias
    biaseff_kernel<<<(B_ * C_ * 32 + 255) / 256, 256>>>(Wo, bo, bve, gamma, be);

    // 9) out[b] = Mp[b] * x[b] + be[b]   (NN, M=512, N=4096, K=512, bias)
    sgemm_kernel<false, false, true><<<dim3(NPIX / BN, C_ / BM, B_), 256>>>(
        Mp, x, out, be, nullptr, C_, NPIX, C_, CC, CN, CN, C_);
}

// round 4
// speedup vs baseline: 2.1007x; 2.1007x over previous
#include <cuda_runtime.h>
#include <cstddef>
#include <cstdint>
#include <math.h>

#define B_   8
#define C_   512
#define NPIX 4096
#define NH   8
#define HD   64

// ---------------- scratch (static device arrays; no allocation) ----------------
__device__ float g_sx  [B_ * C_];            // column sums of x
__device__ float g_Xg  [B_ * C_ * C_];       // Gram per batch
__device__ float g_A2  [B_ * C_ * C_];       // Wq @ Xg per batch
__device__ float g_qs  [B_ * C_];            // Wq @ sx
__device__ float g_ks  [B_ * C_];            // Wk @ sx
__device__ float g_attn[B_ * HD * NH * NH];  // softmax result
__device__ float g_Wve [B_ * C_ * C_];       // effective V projection [m][c]
__device__ float g_WveT[B_ * C_ * C_];       // transposed [c][m]
__device__ float g_bve [B_ * C_];            // effective V bias
__device__ float g_Mp  [B_ * C_ * C_];       // Wo @ Wve (no gamma, no I)
__device__ float g_be  [B_ * C_];            // final effective bias
__device__ float g_xT  [B_ * C_ * NPIX];     // x transposed per batch: [n][c]

__device__ __forceinline__ uint32_t tf32r(float f) {
    uint32_t r;
    asm("cvt.rna.tf32.f32 %0, %1;" : "=r"(r) : "f"(f));
    return r;
}

__device__ __forceinline__ void mma_tf32_16x8x8(
    float& c0, float& c1, float& c2, float& c3,
    uint32_t a0, uint32_t a1, uint32_t a2, uint32_t a3,
    uint32_t b0, uint32_t b1)
{
    asm volatile(
        "mma.sync.aligned.m16n8k8.row.col.f32.tf32.tf32.f32 "
        "{%0,%1,%2,%3}, {%4,%5,%6,%7}, {%8,%9}, {%0,%1,%2,%3};"
        : "+f"(c0), "+f"(c1), "+f"(c2), "+f"(c3)
        : "r"(a0), "r"(a1), "r"(a2), "r"(a3), "r"(b0), "r"(b1));
}

// ---------------- warp-MMA tf32 NT GEMM ----------------
// D[M,N] = A[M,K] * B[N,K]^T  (both K-major), batched over grid.z.
// CTA tile 128x128, 8 warps (2x4), warp tile 64x32, mma m16n8k8, BK=16.
// EPI==0: store D.  EPI==1: store gamma*D + bias[row] + xres[row][col].
constexpr int PAD = 20;     // floats per SMEM row (16 data + 4 pad) -> conflict-free frags

template <int EPI>
__global__ void __launch_bounds__(256, 1) mma_gemm(
    const float* __restrict__ A, const float* __restrict__ Bm, float* __restrict__ Cm,
    const float* __restrict__ bias, const float* __restrict__ gamma_ptr,
    const float* __restrict__ xres,
    int ldA, int ldB, int N, int K,
    size_t sA, size_t sB, size_t sC, size_t sBias)
{
    __shared__ uint32_t As[2][128 * PAD];
    __shared__ uint32_t Bs[2][128 * PAD];

    const int tid = threadIdx.x;
    const int wid = tid >> 5;
    const int lid = tid & 31;
    const int wm = wid >> 2;          // 0..1  (M sub-block of 64)
    const int wn = wid & 3;           // 0..3  (N sub-block of 32)
    const int bz = blockIdx.z;
    const float* Ab = A  + (size_t)bz * sA;
    const float* Bb = Bm + (size_t)bz * sB;
    float*       Cb = Cm + (size_t)bz * sC;
    const int m0 = blockIdx.y * 128;
    const int n0 = blockIdx.x * 128;

    // staging indices: 2 iterations x 256 threads cover 128 rows x 4 float4 cols
    int mrow[2], kc[2];
    #pragma unroll
    for (int it = 0; it < 2; it++) {
        const int idx = it * 256 + tid;
        mrow[it] = idx >> 2;          // 0..127
        kc[it]   = (idx & 3) * 4;     // 0,4,8,12
    }

    float c[4][4][4];
    #pragma unroll
    for (int mt = 0; mt < 4; mt++)
        #pragma unroll
        for (int nt = 0; nt < 4; nt++)
            #pragma unroll
            for (int q = 0; q < 4; q++) c[mt][nt][q] = 0.f;

    const int nCh = K >> 4;
    float4 va[2], vb[2];

    // prologue: chunk 0
    #pragma unroll
    for (int it = 0; it < 2; it++) {
        va[it] = *(const float4*)(Ab + (size_t)(m0 + mrow[it]) * ldA + kc[it]);
        vb[it] = *(const float4*)(Bb + (size_t)(n0 + mrow[it]) * ldB + kc[it]);
    }
    #pragma unroll
    for (int it = 0; it < 2; it++) {
        uint32_t* pa = &As[0][mrow[it] * PAD + kc[it]];
        pa[0] = tf32r(va[it].x); pa[1] = tf32r(va[it].y);
        pa[2] = tf32r(va[it].z); pa[3] = tf32r(va[it].w);
        uint32_t* pb = &Bs[0][mrow[it] * PAD + kc[it]];
        pb[0] = tf32r(vb[it].x); pb[1] = tf32r(vb[it].y);
        pb[2] = tf32r(vb[it].z); pb[3] = tf32r(vb[it].w);
    }
    __syncthreads();

    for (int ic = 0; ic < nCh; ic++) {
        const int cur = ic & 1;
        const bool has_next = (ic + 1 < nCh);
        if (has_next) {
            const int k0 = (ic + 1) << 4;
            #pragma unroll
            for (int it = 0; it < 2; it++) {
                va[it] = *(const float4*)(Ab + (size_t)(m0 + mrow[it]) * ldA + (k0 + kc[it]));
                vb[it] = *(const float4*)(Bb + (size_t)(n0 + mrow[it]) * ldB + (k0 + kc[it]));
            }
        }

        #pragma unroll
        for (int ks = 0; ks < 2; ks++) {
            uint32_t a[4][4], b[4][2];
            const int kb = ks * 8 + (lid & 3);
            #pragma unroll
            for (int mt = 0; mt < 4; mt++) {
                const int r = wm * 64 + mt * 16 + (lid >> 2);
                a[mt][0] = As[cur][(r    ) * PAD + kb    ];
                a[mt][1] = As[cur][(r + 8) * PAD + kb    ];
                a[mt][2] = As[cur][(r    ) * PAD + kb + 4];
                a[mt][3] = As[cur][(r + 8) * PAD + kb + 4];
            }
            #pragma unroll
            for (int nt = 0; nt < 4; nt++) {
                const int n = wn * 32 + nt * 8 + (lid >> 2);
                b[nt][0] = Bs[cur][n * PAD + kb    ];
                b[nt][1] = Bs[cur][n * PAD + kb + 4];
            }
            #pragma unroll
            for (int mt = 0; mt < 4; mt++)
                #pragma unroll
                for (int nt = 0; nt < 4; nt++)
                    mma_tf32_16x8x8(c[mt][nt][0], c[mt][nt][1], c[mt][nt][2], c[mt][nt][3],
                                    a[mt][0], a[mt][1], a[mt][2], a[mt][3],
                                    b[nt][0], b[nt][1]);
        }

        if (has_next) {
            __syncthreads();
            const int nxt = cur ^ 1;
            #pragma unroll
            for (int it = 0; it < 2; it++) {
                uint32_t* pa = &As[nxt][mrow[it] * PAD + kc[it]];
                pa[0] = tf32r(va[it].x); pa[1] = tf32r(va[it].y);
                pa[2] = tf32r(va[it].z); pa[3] = tf32r(va[it].w);
                uint32_t* pb = &Bs[nxt][mrow[it] * PAD + kc[it]];
                pb[0] = tf32r(vb[it].x); pb[1] = tf32r(vb[it].y);
                pb[2] = tf32r(vb[it].z); pb[3] = tf32r(vb[it].w);
            }
            __syncthreads();
        }
    }

    // epilogue
    float gam = 0.f;
    if (EPI == 1) gam = gamma_ptr[0];
    #pragma unroll
    for (int mt = 0; mt < 4; mt++) {
        const int row = m0 + wm * 64 + mt * 16 + (lid >> 2);
        float bv0 = 0.f, bv1 = 0.f;
        if (EPI == 1) {
            bv0 = bias[(size_t)bz * sBias + row];
            bv1 = bias[(size_t)bz * sBias + row + 8];
        }
        #pragma unroll
        for (int nt = 0; nt < 4; nt++) {
            const int col = n0 + wn * 32 + nt * 8 + (lid & 3) * 2;
            if (EPI == 0) {
                float2 v0 = { c[mt][nt][0], c[mt][nt][1] };
                float2 v1 = { c[mt][nt][2], c[mt][nt][3] };
                *(float2*)(Cb + (size_t)row * N + col)       = v0;
                *(float2*)(Cb + (size_t)(row + 8) * N + col) = v1;
            } else {
                const float* xr0 = xres + (size_t)bz * sC + (size_t)row * N + col;
                const float* xr1 = xres + (size_t)bz * sC + (size_t)(row + 8) * N + col;
                float2 x0 = *(const float2*)xr0;
                float2 x1 = *(const float2*)xr1;
                float2 v0 = { gam * c[mt][nt][0] + bv0 + x0.x,
                              gam * c[mt][nt][1] + bv0 + x0.y };
                float2 v1 = { gam * c[mt][nt][2] + bv1 + x1.x,
                              gam * c[mt][nt][3] + bv1 + x1.y };
                *(float2*)(Cb + (size_t)row * N + col)       = v0;
                *(float2*)(Cb + (size_t)(row + 8) * N + col) = v1;
            }
        }
    }
}

// ---------------- transpose: dst[c][r] = src[r][c], batched over grid.z ----------------
__global__ void transpose_kernel(const float* __restrict__ src, float* __restrict__ dst,
                                 int R, int Cc, size_t strideS, size_t strideD)
{
    __shared__ float t[32][33];
    const float* s = src + (size_t)blockIdx.z * strideS;
    float*       d = dst + (size_t)blockIdx.z * strideD;
    const int c0 = blockIdx.x * 32;
    const int r0 = blockIdx.y * 32;
    #pragma unroll
    for (int i = 0; i < 32; i += 8)
        t[threadIdx.y + i][threadIdx.x] = s[(size_t)(r0 + threadIdx.y + i) * Cc + c0 + threadIdx.x];
    __syncthreads();
    #pragma unroll
    for (int i = 0; i < 32; i += 8)
        d[(size_t)(c0 + threadIdx.y + i) * R + r0 + threadIdx.x] = t[threadIdx.x][threadIdx.y + i];
}

// ---------------- small kernels ----------------
__global__ void colsum_kernel(const float* __restrict__ x, float* __restrict__ sx)
{
    const int c = blockIdx.x, b = blockIdx.y;
    const float* p = x + ((size_t)b * C_ + c) * NPIX;
    float s = 0.f;
    for (int n = threadIdx.x; n < NPIX; n += 256) s += p[n];
    __shared__ float red[256];
    red[threadIdx.x] = s;
    __syncthreads();
    for (int off = 128; off > 0; off >>= 1) {
        if (threadIdx.x < off) red[threadIdx.x] += red[threadIdx.x + off];
        __syncthreads();
    }
    if (threadIdx.x == 0) sx[b * C_ + c] = red[0];
}

__global__ void projsum_kernel(const float* __restrict__ Wq, const float* __restrict__ Wk,
                               const float* __restrict__ sx,
                               float* __restrict__ qs, float* __restrict__ ks)
{
    const int gw   = (blockIdx.x * blockDim.x + threadIdx.x) >> 5;
    const int lane = threadIdx.x & 31;
    if (gw >= 2 * B_ * C_) return;
    const int which = gw >> 12;
    const int idx = gw & 4095;
    const int b = idx >> 9, c = idx & 511;
    const float* W = which ? Wk : Wq;
    const float* s = sx + b * C_;
    float acc = 0.f;
    for (int k = lane; k < C_; k += 32) acc += W[(size_t)c * C_ + k] * s[k];
    #pragma unroll
    for (int off = 16; off; off >>= 1) acc += __shfl_down_sync(0xffffffffu, acc, off);
    if (lane == 0) (which ? ks : qs)[b * C_ + c] = acc;
}

__global__ void attn_kernel(const float* __restrict__ A2, const float* __restrict__ Wk,
                            const float* __restrict__ bq, const float* __restrict__ bk,
                            const float* __restrict__ qs, const float* __restrict__ ks,
                            float* __restrict__ attn)
{
    const int bid = blockIdx.x;           // ((b*64+d)*8+i)
    const int i = bid & 7;
    const int bd = bid >> 3;
    const int d = bd & 63, b = bd >> 6;
    const int j = threadIdx.x >> 5, lane = threadIdx.x & 31;
    const int id = i * HD + d, jd = j * HD + d;

    const float* a2 = A2 + ((size_t)b * C_ + id) * C_;
    const float* wk = Wk + (size_t)jd * C_;
    float acc = 0.f;
    for (int c = lane; c < C_; c += 32) acc += a2[c] * wk[c];
    #pragma unroll
    for (int off = 16; off; off >>= 1) acc += __shfl_down_sync(0xffffffffu, acc, off);

    __shared__ float Sj[NH];
    if (lane == 0) {
        float s = acc + bq[id] * ks[b * C_ + jd] + qs[b * C_ + id] * bk[jd]
                + (float)NPIX * bq[id] * bk[jd];
        Sj[j] = s * 0.125f;
    }
    __syncthreads();
    if (threadIdx.x < NH) {
        float mx = -1e30f;
        #pragma unroll
        for (int t = 0; t < NH; t++) mx = fmaxf(mx, Sj[t]);
        float sum = 0.f;
        #pragma unroll
        for (int t = 0; t < NH; t++) sum += expf(Sj[t] - mx);
        attn[(size_t)bid * NH + threadIdx.x] = expf(Sj[threadIdx.x] - mx) / sum;
    }
}

__global__ void wve_kernel(const float* __restrict__ Wv, const float* __restrict__ bv,
                           const float* __restrict__ attn,
                           float* __restrict__ Wve, float* __restrict__ bve)
{
    const int m = blockIdx.x, b = blockIdx.y;
    const int d = m & 63, i = m >> 6;
    const float* at = attn + (((size_t)b * HD + d) * NH + i) * NH;
    float a[NH];
    #pragma unroll
    for (int j = 0; j < NH; j++) a[j] = at[j];

    for (int c = threadIdx.x; c < C_; c += 256) {
        float acc = 0.f;
        #pragma unroll
        for (int j = 0; j < NH; j++) acc += a[j] * Wv[(size_t)(j * HD + d) * C_ + c];
        Wve[((size_t)b * C_ + m) * C_ + c] = acc;
    }
    if (threadIdx.x == 0) {
        float accb = 0.f;
        #pragma unroll
        for (int j = 0; j < NH; j++) accb += a[j] * bv[j * HD + d];
        bve[b * C_ + m] = accb;
    }
}

__global__ void biaseff_kernel(const float* __restrict__ Wo, const float* __restrict__ bo,
                               const float* __restrict__ bve, const float* __restrict__ gamma,
                               float* __restrict__ be)
{
    const int gw   = (blockIdx.x * blockDim.x + threadIdx.x) >> 5;
    const int lane = threadIdx.x & 31;
    if (gw >= B_ * C_) return;
    const int b = gw >> 9, o = gw & 511;
    float acc = 0.f;
    for (int mm = lane; mm < C_; mm += 32) acc += Wo[(size_t)o * C_ + mm] * bve[b * C_ + mm];
    #pragma unroll
    for (int off = 16; off; off >>= 1) acc += __shfl_down_sync(0xffffffffu, acc, off);
    if (lane == 0) be[b * C_ + o] = gamma[0] * acc + bo[o];
}

// ---------------- launch ----------------
extern "C" void kernel_launch(void* const* d_in, const int* in_sizes, int n_in,
                              void* d_out, int out_size)
{
    (void)in_sizes; (void)n_in; (void)out_size;
    const float* x     = (const float*)d_in[0];
    const float* Wq    = (const float*)d_in[1];
    const float* bq    = (const float*)d_in[2];
    const float* Wk    = (const float*)d_in[3];
    const float* bk    = (const float*)d_in[4];
    const float* Wv    = (const float*)d_in[5];
    const float* bv    = (const float*)d_in[6];
    const float* Wo    = (const float*)d_in[7];
    const float* bo    = (const float*)d_in[8];
    const float* gamma = (const float*)d_in[9];
    float* out = (float*)d_out;

    float *sx, *Xg, *A2, *qs, *ks, *attn, *Wve, *WveT, *bve, *Mp, *be, *xT;
    cudaGetSymbolAddress((void**)&sx,   g_sx);
    cudaGetSymbolAddress((void**)&Xg,   g_Xg);
    cudaGetSymbolAddress((void**)&A2,   g_A2);
    cudaGetSymbolAddress((void**)&qs,   g_qs);
    cudaGetSymbolAddress((void**)&ks,   g_ks);
    cudaGetSymbolAddress((void**)&attn, g_attn);
    cudaGetSymbolAddress((void**)&Wve,  g_Wve);
    cudaGetSymbolAddress((void**)&WveT, g_WveT);
    cudaGetSymbolAddress((void**)&bve,  g_bve);
    cudaGetSymbolAddress((void**)&Mp,   g_Mp);
    cudaGetSymbolAddress((void**)&be,   g_be);
    cudaGetSymbolAddress((void**)&xT,   g_xT);

    const size_t CN = (size_t)C_ * NPIX;   // per-batch x stride
    const size_t CC = (size_t)C_ * C_;

    // 1) column sums + x transpose (xT[b][n][c])
    colsum_kernel<<<dim3(C_, B_), 256>>>(x, sx);
    transpose_kernel<<<dim3(NPIX / 32, C_ / 32, B_), dim3(32, 8)>>>(x, xT, C_, NPIX, CN, CN);

    // 2) Gram: Xg[b] = x_b * x_b^T   (NT, M=N=512, K=4096)
    mma_gemm<0><<<dim3(4, 4, B_), 256>>>(
        x, x, Xg, nullptr, nullptr, nullptr, NPIX, NPIX, C_, NPIX, CN, CN, CC, 0);

    // 3) projected sums
    projsum_kernel<<<(2 * B_ * C_ * 32 + 255) / 256, 256>>>(Wq, Wk, sx, qs, ks);

    // 4) A2[b] = Wq * Xg[b]  (Xg symmetric -> NT works)
    mma_gemm<0><<<dim3(4, 4, B_), 256>>>(
        Wq, Xg, A2, nullptr, nullptr, nullptr, C_, C_, C_, C_, 0, CC, CC, 0);

    // 5) logits + softmax -> attn
    attn_kernel<<<B_ * HD * NH, 256>>>(A2, Wk, bq, bk, qs, ks, attn);

    // 6) effective V projection, then transpose
    wve_kernel<<<dim3(C_, B_), 256>>>(Wv, bv, attn, Wve, bve);
    transpose_kernel<<<dim3(C_ / 32, C_ / 32, B_), dim3(32, 8)>>>(Wve, WveT, C_, C_, CC, CC);

    // 7) Mp[b] = Wo * Wve[b]   (NT with B = WveT)
    mma_gemm<0><<<dim3(4, 4, B_), 256>>>(
        Wo, WveT, Mp, nullptr, nullptr, nullptr, C_, C_, C_, C_, 0, CC, CC, 0);

    // 8) effective bias (includes gamma and bo)
    biaseff_kernel<<<(B_ * C_ * 32 + 255) / 256, 256>>>(Wo, bo, bve, gamma, be);

    // 9) out[b] = gamma * (Mp[b] * x[b]) + be[b] + x[b]   (NT with B = xT, fused epilogue)
    mma_gemm<1><<<dim3(NPIX / 128, 4, B_), 256>>>(
        Mp, xT, out, be, gamma, x, C_, C_, NPIX, C_, CC, CN, CN, C_);
}

// round 7
// speedup vs baseline: 3.0090x; 1.4323x over previous
#include <cuda_runtime.h>
#include <cstddef>
#include <cstdint>
#include <math.h>

#define B_   8
#define C_   512
#define NPIX 4096
#define NH   8
#define HD   64

// ---------------- scratch (static device arrays; no allocation) ----------------
__device__ float g_sx  [B_ * C_];            // column sums of x
__device__ float g_Xg  [B_ * C_ * C_];       // Gram per batch
__device__ float g_A2  [B_ * C_ * C_];       // Wq @ Xg per batch
__device__ float g_qs  [B_ * C_];            // Wq @ sx
__device__ float g_ks  [B_ * C_];            // Wk @ sx
__device__ float g_attn[B_ * HD * NH * NH];  // softmax result
__device__ float g_Wve [B_ * C_ * C_];       // effective V projection [m][c]
__device__ float g_WveT[B_ * C_ * C_];       // transposed [c][m]
__device__ float g_bve [B_ * C_];            // effective V bias
__device__ float g_Mp  [B_ * C_ * C_];       // Wo @ Wve (no gamma, no I)
__device__ float g_be  [B_ * C_];            // final effective bias
__device__ float g_xT  [B_ * C_ * NPIX];     // x transposed per batch: [n][c]

__device__ __forceinline__ void mma_tf32_16x8x8(
    float& c0, float& c1, float& c2, float& c3,
    uint32_t a0, uint32_t a1, uint32_t a2, uint32_t a3,
    uint32_t b0, uint32_t b1)
{
    asm volatile(
        "mma.sync.aligned.m16n8k8.row.col.f32.tf32.tf32.f32 "
        "{%0,%1,%2,%3}, {%4,%5,%6,%7}, {%8,%9}, {%0,%1,%2,%3};"
        : "+f"(c0), "+f"(c1), "+f"(c2), "+f"(c3)
        : "r"(a0), "r"(a1), "r"(a2), "r"(a3), "r"(b0), "r"(b1));
}

__device__ __forceinline__ uint32_t smem_u32(const void* p) {
    uint32_t a;
    asm("{ .reg .u64 t; cvta.to.shared.u64 t, %1; cvt.u32.u64 %0, t; }" : "=r"(a) : "l"(p));
    return a;
}

// ---------------- warp-MMA tf32 NT GEMM, cp.async 4-stage pipeline ----------------
// D[M,N] = A[M,K] * B[N,K]^T  (both K-major), batched over grid.z.
// CTA tile 128x128, 8 warps (2x4), warp tile 64x32, mma m16n8k8, BK=16, 4 stages.
// fp32 operands fed raw to tf32 MMA (HW truncates low mantissa bits).
// EPI==0: store D.  EPI==1: store gamma*D + bias[row] + xres[row][col].
constexpr int PAD = 20;            // u32 per SMEM row (16 data + 4 pad) -> conflict-free
constexpr int STAGE_U32 = 128 * PAD;        // 2560 u32 = 10240 B per tile stage
constexpr int BSTAGE_OFF = 4 * STAGE_U32;   // B region starts after 4 A stages
constexpr int SMEM_BYTES = 8 * STAGE_U32 * 4;  // 81920 B

template <int EPI>
__global__ void __launch_bounds__(256, 2) mma_gemm(
    const float* __restrict__ A, const float* __restrict__ Bm, float* __restrict__ Cm,
    const float* __restrict__ bias, const float* __restrict__ gamma_ptr,
    const float* __restrict__ xres,
    int ldA, int ldB, int N, int K,
    size_t sA, size_t sB, size_t sC, size_t sBias)
{
    extern __shared__ __align__(16) uint32_t sm[];
    const uint32_t smA_addr = smem_u32(sm);
    const uint32_t smB_addr = smA_addr + BSTAGE_OFF * 4;

    const int tid = threadIdx.x;
    const int wid = tid >> 5;
    const int lid = tid & 31;
    const int wm = wid >> 2;          // 0..1  (M sub-block of 64)
    const int wn = wid & 3;           // 0..3  (N sub-block of 32)
    const int bz = blockIdx.z;
    const float* Ab = A  + (size_t)bz * sA;
    const float* Bb = Bm + (size_t)bz * sB;
    float*       Cb = Cm + (size_t)bz * sC;
    const int m0 = blockIdx.y * 128;
    const int n0 = blockIdx.x * 128;

    // staging: 2 iterations x 256 threads cover 128 rows x 4 x 16B
    int mrow[2], kcf[2];
    #pragma unroll
    for (int it = 0; it < 2; it++) {
        const int idx = it * 256 + tid;
        mrow[it] = idx >> 2;          // 0..127
        kcf[it]  = (idx & 3) * 4;     // 0,4,8,12 (floats)
    }

    float c[4][4][4];
    #pragma unroll
    for (int mt = 0; mt < 4; mt++)
        #pragma unroll
        for (int nt = 0; nt < 4; nt++)
            #pragma unroll
            for (int q = 0; q < 4; q++) c[mt][nt][q] = 0.f;

    const int nCh = K >> 4;   // K-chunks of 16 (always >= 32 here)

    auto issue_stage = [&](int buf, int k0) {
        #pragma unroll
        for (int it = 0; it < 2; it++) {
            const float* ga = Ab + (size_t)(m0 + mrow[it]) * ldA + (k0 + kcf[it]);
            uint32_t da = smA_addr + (uint32_t)((buf * STAGE_U32 + mrow[it] * PAD + kcf[it]) * 4);
            asm volatile("cp.async.cg.shared.global [%0], [%1], 16;" :: "r"(da), "l"(ga));
            const float* gb = Bb + (size_t)(n0 + mrow[it]) * ldB + (k0 + kcf[it]);
            uint32_t db = smB_addr + (uint32_t)((buf * STAGE_U32 + mrow[it] * PAD + kcf[it]) * 4);
            asm volatile("cp.async.cg.shared.global [%0], [%1], 16;" :: "r"(db), "l"(gb));
        }
        asm volatile("cp.async.commit_group;" ::: "memory");
    };

    // prologue: 3 stages in flight
    issue_stage(0, 0);
    issue_stage(1, 16);
    issue_stage(2, 32);

    for (int ic = 0; ic < nCh; ic++) {
        asm volatile("cp.async.wait_group 2;" ::: "memory");
        __syncthreads();

        const int cur = ic & 3;
        const uint32_t* As = sm + cur * STAGE_U32;
        const uint32_t* Bs = sm + BSTAGE_OFF + cur * STAGE_U32;

        #pragma unroll
        for (int ks = 0; ks < 2; ks++) {
            uint32_t a[4][4], b[4][2];
            const int kb = ks * 8 + (lid & 3);
            #pragma unroll
            for (int mt = 0; mt < 4; mt++) {
                const int r = wm * 64 + mt * 16 + (lid >> 2);
                a[mt][0] = As[(r    ) * PAD + kb    ];
                a[mt][1] = As[(r + 8) * PAD + kb    ];
                a[mt][2] = As[(r    ) * PAD + kb + 4];
                a[mt][3] = As[(r + 8) * PAD + kb + 4];
            }
            #pragma unroll
            for (int nt = 0; nt < 4; nt++) {
                const int n = wn * 32 + nt * 8 + (lid >> 2);
                b[nt][0] = Bs[n * PAD + kb    ];
                b[nt][1] = Bs[n * PAD + kb + 4];
            }
            #pragma unroll
            for (int mt = 0; mt < 4; mt++)
                #pragma unroll
                for (int nt = 0; nt < 4; nt++)
                    mma_tf32_16x8x8(c[mt][nt][0], c[mt][nt][1], c[mt][nt][2], c[mt][nt][3],
                                    a[mt][0], a[mt][1], a[mt][2], a[mt][3],
                                    b[nt][0], b[nt][1]);
        }

        if (ic + 3 < nCh) {
            issue_stage((ic + 3) & 3, (ic + 3) << 4);
        } else {
            asm volatile("cp.async.commit_group;" ::: "memory");  // keep group count consistent
        }
    }

    // epilogue
    float gam = 0.f;
    if (EPI == 1) gam = gamma_ptr[0];
    #pragma unroll
    for (int mt = 0; mt < 4; mt++) {
        const int row = m0 + wm * 64 + mt * 16 + (lid >> 2);
        float bv0 = 0.f, bv1 = 0.f;
        if (EPI == 1) {
            bv0 = bias[(size_t)bz * sBias + row];
            bv1 = bias[(size_t)bz * sBias + row + 8];
        }
        #pragma unroll
        for (int nt = 0; nt < 4; nt++) {
            const int col = n0 + wn * 32 + nt * 8 + (lid & 3) * 2;
            if (EPI == 0) {
                float2 v0 = { c[mt][nt][0], c[mt][nt][1] };
                float2 v1 = { c[mt][nt][2], c[mt][nt][3] };
                *(float2*)(Cb + (size_t)row * N + col)       = v0;
                *(float2*)(Cb + (size_t)(row + 8) * N + col) = v1;
            } else {
                const float* xr0 = xres + (size_t)bz * sC + (size_t)row * N + col;
                const float* xr1 = xres + (size_t)bz * sC + (size_t)(row + 8) * N + col;
                float2 x0 = *(const float2*)xr0;
                float2 x1 = *(const float2*)xr1;
                float2 v0 = { gam * c[mt][nt][0] + bv0 + x0.x,
                              gam * c[mt][nt][1] + bv0 + x0.y };
                float2 v1 = { gam * c[mt][nt][2] + bv1 + x1.x,
                              gam * c[mt][nt][3] + bv1 + x1.y };
                *(float2*)(Cb + (size_t)row * N + col)       = v0;
                *(float2*)(Cb + (size_t)(row + 8) * N + col) = v1;
            }
        }
    }
}

// ---------------- transpose: dst[c][r] = src[r][c], batched over grid.z ----------------
__global__ void transpose_kernel(const float* __restrict__ src, float* __restrict__ dst,
                                 int R, int Cc, size_t strideS, size_t strideD)
{
    __shared__ float t[32][33];
    const float* s = src + (size_t)blockIdx.z * strideS;
    float*       d = dst + (size_t)blockIdx.z * strideD;
    const int c0 = blockIdx.x * 32;
    const int r0 = blockIdx.y * 32;
    #pragma unroll
    for (int i = 0; i < 32; i += 8)
        t[threadIdx.y + i][threadIdx.x] = s[(size_t)(r0 + threadIdx.y + i) * Cc + c0 + threadIdx.x];
    __syncthreads();
    #pragma unroll
    for (int i = 0; i < 32; i += 8)
        d[(size_t)(c0 + threadIdx.y + i) * R + r0 + threadIdx.x] = t[threadIdx.x][threadIdx.y + i];
}

// ---------------- small kernels ----------------
__global__ void colsum_kernel(const float* __restrict__ x, float* __restrict__ sx)
{
    const int c = blockIdx.x, b = blockIdx.y;
    const float* p = x + ((size_t)b * C_ + c) * NPIX;
    float s = 0.f;
    for (int n = threadIdx.x; n < NPIX; n += 256) s += p[n];
    __shared__ float red[256];
    red[threadIdx.x] = s;
    __syncthreads();
    for (int off = 128; off > 0; off >>= 1) {
        if (threadIdx.x < off) red[threadIdx.x] += red[threadIdx.x + off];
        __syncthreads();
    }
    if (threadIdx.x == 0) sx[b * C_ + c] = red[0];
}

__global__ void projsum_kernel(const float* __restrict__ Wq, const float* __restrict__ Wk,
                               const float* __restrict__ sx,
                               float* __restrict__ qs, float* __restrict__ ks)
{
    const int gw   = (blockIdx.x * blockDim.x + threadIdx.x) >> 5;
    const int lane = threadIdx.x & 31;
    if (gw >= 2 * B_ * C_) return;
    const int which = gw >> 12;
    const int idx = gw & 4095;
    const int b = idx >> 9, c = idx & 511;
    const float* W = which ? Wk : Wq;
    const float* s = sx + b * C_;
    float acc = 0.f;
    for (int k = lane; k < C_; k += 32) acc += W[(size_t)c * C_ + k] * s[k];
    #pragma unroll
    for (int off = 16; off; off >>= 1) acc += __shfl_down_sync(0xffffffffu, acc, off);
    if (lane == 0) (which ? ks : qs)[b * C_ + c] = acc;
}

__global__ void attn_kernel(const float* __restrict__ A2, const float* __restrict__ Wk,
                            const float* __restrict__ bq, const float* __restrict__ bk,
                            const float* __restrict__ qs, const float* __restrict__ ks,
                            float* __restrict__ attn)
{
    const int bid = blockIdx.x;           // ((b*64+d)*8+i)
    const int i = bid & 7;
    const int bd = bid >> 3;
    const int d = bd & 63, b = bd >> 6;
    const int j = threadIdx.x >> 5, lane = threadIdx.x & 31;
    const int id = i * HD + d, jd = j * HD + d;

    const float* a2 = A2 + ((size_t)b * C_ + id) * C_;
    const float* wk = Wk + (size_t)jd * C_;
    float acc = 0.f;
    for (int c = lane; c < C_; c += 32) acc += a2[c] * wk[c];
    #pragma unroll
    for (int off = 16; off; off >>= 1) acc += __shfl_down_sync(0xffffffffu, acc, off);

    __shared__ float Sj[NH];
    if (lane == 0) {
        float s = acc + bq[id] * ks[b * C_ + jd] + qs[b * C_ + id] * bk[jd]
                + (float)NPIX * bq[id] * bk[jd];
        Sj[j] = s * 0.125f;
    }
    __syncthreads();
    if (threadIdx.x < NH) {
        float mx = -1e30f;
        #pragma unroll
        for (int t = 0; t < NH; t++) mx = fmaxf(mx, Sj[t]);
        float sum = 0.f;
        #pragma unroll
        for (int t = 0; t < NH; t++) sum += expf(Sj[t] - mx);
        attn[(size_t)bid * NH + threadIdx.x] = expf(Sj[threadIdx.x] - mx) / sum;
    }
}

__global__ void wve_kernel(const float* __restrict__ Wv, const float* __restrict__ bv,
                           const float* __restrict__ attn,
                           float* __restrict__ Wve, float* __restrict__ bve)
{
    const int m = blockIdx.x, b = blockIdx.y;
    const int d = m & 63, i = m >> 6;
    const float* at = attn + (((size_t)b * HD + d) * NH + i) * NH;
    float a[NH];
    #pragma unroll
    for (int j = 0; j < NH; j++) a[j] = at[j];

    for (int c = threadIdx.x; c < C_; c += 256) {
        float acc = 0.f;
        #pragma unroll
        for (int j = 0; j < NH; j++) acc += a[j] * Wv[(size_t)(j * HD + d) * C_ + c];
        Wve[((size_t)b * C_ + m) * C_ + c] = acc;
    }
    if (threadIdx.x == 0) {
        float accb = 0.f;
        #pragma unroll
        for (int j = 0; j < NH; j++) accb += a[j] * bv[j * HD + d];
        bve[b * C_ + m] = accb;
    }
}

__global__ void biaseff_kernel(const float* __restrict__ Wo, const float* __restrict__ bo,
                               const float* __restrict__ bve, const float* __restrict__ gamma,
                               float* __restrict__ be)
{
    const int gw   = (blockIdx.x * blockDim.x + threadIdx.x) >> 5;
    const int lane = threadIdx.x & 31;
    if (gw >= B_ * C_) return;
    const int b = gw >> 9, o = gw & 511;
    float acc = 0.f;
    for (int mm = lane; mm < C_; mm += 32) acc += Wo[(size_t)o * C_ + mm] * bve[b * C_ + mm];
    #pragma unroll
    for (int off = 16; off; off >>= 1) acc += __shfl_down_sync(0xffffffffu, acc, off);
    if (lane == 0) be[b * C_ + o] = gamma[0] * acc + bo[o];
}

// ---------------- launch ----------------
extern "C" void kernel_launch(void* const* d_in, const int* in_sizes, int n_in,
                              void* d_out, int out_size)
{
    (void)in_sizes; (void)n_in; (void)out_size;
    const float* x     = (const float*)d_in[0];
    const float* Wq    = (const float*)d_in[1];
    const float* bq    = (const float*)d_in[2];
    const float* Wk    = (const float*)d_in[3];
    const float* bk    = (const float*)d_in[4];
    const float* Wv    = (const float*)d_in[5];
    const float* bv    = (const float*)d_in[6];
    const float* Wo    = (const float*)d_in[7];
    const float* bo    = (const float*)d_in[8];
    const float* gamma = (const float*)d_in[9];
    float* out = (float*)d_out;

    float *sx, *Xg, *A2, *qs, *ks, *attn, *Wve, *WveT, *bve, *Mp, *be, *xT;
    cudaGetSymbolAddress((void**)&sx,   g_sx);
    cudaGetSymbolAddress((void**)&Xg,   g_Xg);
    cudaGetSymbolAddress((void**)&A2,   g_A2);
    cudaGetSymbolAddress((void**)&qs,   g_qs);
    cudaGetSymbolAddress((void**)&ks,   g_ks);
    cudaGetSymbolAddress((void**)&attn, g_attn);
    cudaGetSymbolAddress((void**)&Wve,  g_Wve);
    cudaGetSymbolAddress((void**)&WveT, g_WveT);
    cudaGetSymbolAddress((void**)&bve,  g_bve);
    cudaGetSymbolAddress((void**)&Mp,   g_Mp);
    cudaGetSymbolAddress((void**)&be,   g_be);
    cudaGetSymbolAddress((void**)&xT,   g_xT);

    cudaFuncSetAttribute(mma_gemm<0>, cudaFuncAttributeMaxDynamicSharedMemorySize, SMEM_BYTES);
    cudaFuncSetAttribute(mma_gemm<1>, cudaFuncAttributeMaxDynamicSharedMemorySize, SMEM_BYTES);

    const size_t CN = (size_t)C_ * NPIX;   // per-batch x stride
    const size_t CC = (size_t)C_ * C_;

    // 1) column sums + x transpose (xT[b][n][c])
    colsum_kernel<<<dim3(C_, B_), 256>>>(x, sx);
    transpose_kernel<<<dim3(NPIX / 32, C_ / 32, B_), dim3(32, 8)>>>(x, xT, C_, NPIX, CN, CN);

    // 2) Gram: Xg[b] = x_b * x_b^T   (NT, M=N=512, K=4096)
    mma_gemm<0><<<dim3(4, 4, B_), 256, SMEM_BYTES>>>(
        x, x, Xg, nullptr, nullptr, nullptr, NPIX, NPIX, C_, NPIX, CN, CN, CC, 0);

    // 3) projected sums
    projsum_kernel<<<(2 * B_ * C_ * 32 + 255) / 256, 256>>>(Wq, Wk, sx, qs, ks);

    // 4) A2[b] = Wq * Xg[b]  (Xg symmetric -> NT works)
    mma_gemm<0><<<dim3(4, 4, B_), 256, SMEM_BYTES>>>(
        Wq, Xg, A2, nullptr, nullptr, nullptr, C_, C_, C_, C_, 0, CC, CC, 0);

    // 5) logits + softmax -> attn
    attn_kernel<<<B_ * HD * NH, 256>>>(A2, Wk, bq, bk, qs, ks, attn);

    // 6) effective V projection, then transpose
    wve_kernel<<<dim3(C_, B_), 256>>>(Wv, bv, attn, Wve, bve);
    transpose_kernel<<<dim3(C_ / 32, C_ / 32, B_), dim3(32, 8)>>>(Wve, WveT, C_, C_, CC, CC);

    // 7) Mp[b] = Wo * Wve[b]   (NT with B = WveT)
    mma_gemm<0><<<dim3(4, 4, B_), 256, SMEM_BYTES>>>(
        Wo, WveT, Mp, nullptr, nullptr, nullptr, C_, C_, C_, C_, 0, CC, CC, 0);

    // 8) effective bias (includes gamma and bo)
    biaseff_kernel<<<(B_ * C_ * 32 + 255) / 256, 256>>>(Wo, bo, bve, gamma, be);

    // 9) out[b] = gamma * (Mp[b] * x[b]) + be[b] + x[b]   (NT with B = xT, fused epilogue)
    mma_gemm<1><<<dim3(NPIX / 128, 4, B_), 256, SMEM_BYTES>>>(
        Mp, xT, out, be, gamma, x, C_, C_, NPIX, C_, CC, CN, CN, C_);
}